// round 10
// baseline (speedup 1.0000x reference)
#include <cuda_runtime.h>
#include <cstdint>

#define BATCH 32
#define CH    512
#define SP    1024

// Scratch (device globals — no allocation allowed)
__device__ float    g_part[(size_t)BATCH * CH * 16];   // partial channel sums per s-tile
__device__ uint8_t  g_Wq [(size_t)BATCH * CH * CH];    // e4m3: attn[b][k][j] * 256, [b][j][k]
__device__ uint8_t  g_Xq [(size_t)BATCH * SP * CH];    // e4m3: x transposed [b][s][k]

__device__ __forceinline__ uint32_t pack4_e4m3(float f0, float f1, float f2, float f3) {
    uint16_t lo, hi;
    asm("cvt.rn.satfinite.e4m3x2.f32 %0, %1, %2;" : "=h"(lo) : "f"(f1), "f"(f0));
    asm("cvt.rn.satfinite.e4m3x2.f32 %0, %1, %2;" : "=h"(hi) : "f"(f3), "f"(f2));
    return (uint32_t)lo | ((uint32_t)hi << 16);
}

// ---------------------------------------------------------------------------
// Kernel 1: 64(c) x 64(s) tile: fp32 load -> smem -> (a) partial channel sums,
// (b) transposed e4m3 write to g_Xq[b][s][k].
// ---------------------------------------------------------------------------
__global__ void __launch_bounds__(256) prep_kernel(const float* __restrict__ x) {
    __shared__ float sm[64][65];
    int b  = blockIdx.z;
    int c0 = blockIdx.y * 64;
    int s0 = blockIdx.x * 64;
    int tid = threadIdx.x;

    const float* xb = x + ((size_t)b * CH + c0) * SP + s0;
    #pragma unroll
    for (int i = 0; i < 4; ++i) {
        int ch = tid + i * 256;
        int r = ch >> 4, c4 = (ch & 15) * 4;
        float4 v = *reinterpret_cast<const float4*>(xb + (size_t)r * SP + c4);
        sm[r][c4 + 0] = v.x; sm[r][c4 + 1] = v.y;
        sm[r][c4 + 2] = v.z; sm[r][c4 + 3] = v.w;
    }
    __syncthreads();

    if (tid < 64) {
        float s = 0.0f;
        #pragma unroll
        for (int i = 0; i < 64; ++i) s += sm[tid][i];
        g_part[((size_t)b * CH + c0 + tid) * 16 + blockIdx.x] = s;
    }

    // transpose: thread -> (s = tid>>2, k0 = (tid&3)*16), emit 16 e4m3 bytes
    int s  = tid >> 2;
    int k0 = (tid & 3) * 16;
    float f[16];
    #pragma unroll
    for (int i = 0; i < 16; ++i) f[i] = sm[k0 + i][s];
    uint4 pk;
    pk.x = pack4_e4m3(f[0],  f[1],  f[2],  f[3]);
    pk.y = pack4_e4m3(f[4],  f[5],  f[6],  f[7]);
    pk.z = pack4_e4m3(f[8],  f[9],  f[10], f[11]);
    pk.w = pack4_e4m3(f[12], f[13], f[14], f[15]);
    *reinterpret_cast<uint4*>(g_Xq + ((size_t)b * SP + s0 + s) * CH + c0 + k0) = pk;
}

// ---------------------------------------------------------------------------
// Kernel 2: reduce partials -> means; W'[b][j][k] = 256*exp(-(m_j-m_k)^2)/Z_j
// as e4m3. score[j,j]==0 is the exact row max -> raw exp == shifted softmax.
// Lane owns k = lane*16..+15 (contiguous -> one uint4 store per row).
// ---------------------------------------------------------------------------
__global__ void __launch_bounds__(256) attn_kernel() {
    int b  = blockIdx.y;
    int jc = blockIdx.x;
    __shared__ float sm[CH];
    for (int c = threadIdx.x; c < CH; c += 256) {
        const float* p = g_part + ((size_t)b * CH + c) * 16;
        float s = 0.0f;
        #pragma unroll
        for (int i = 0; i < 16; ++i) s += p[i];
        sm[c] = s * (1.0f / SP);
    }
    __syncthreads();

    int warp = threadIdx.x >> 5, lane = threadIdx.x & 31;
    float mk[16];
    #pragma unroll
    for (int i = 0; i < 4; ++i) {
        float4 q = *reinterpret_cast<const float4*>(&sm[lane * 16 + i * 4]);
        mk[i * 4 + 0] = q.x; mk[i * 4 + 1] = q.y;
        mk[i * 4 + 2] = q.z; mk[i * 4 + 3] = q.w;
    }

    for (int jr = 0; jr < 16; ++jr) {
        int j = jc * 128 + warp * 16 + jr;
        float mj = sm[j];
        float e[16];
        float sum = 0.0f;
        #pragma unroll
        for (int kk = 0; kk < 16; ++kk) {
            float d = mj - mk[kk];
            float v = __expf(-d * d);
            e[kk] = v;
            sum += v;
        }
        #pragma unroll
        for (int o = 16; o > 0; o >>= 1) sum += __shfl_xor_sync(0xffffffffu, sum, o);
        float inv256 = 256.0f / sum;
        uint4 pk;
        pk.x = pack4_e4m3(e[0]*inv256,  e[1]*inv256,  e[2]*inv256,  e[3]*inv256);
        pk.y = pack4_e4m3(e[4]*inv256,  e[5]*inv256,  e[6]*inv256,  e[7]*inv256);
        pk.z = pack4_e4m3(e[8]*inv256,  e[9]*inv256,  e[10]*inv256, e[11]*inv256);
        pk.w = pack4_e4m3(e[12]*inv256, e[13]*inv256, e[14]*inv256, e[15]*inv256);
        *reinterpret_cast<uint4*>(g_Wq + ((size_t)b * CH + j) * CH + lane * 16) = pk;
    }
}

// ---------------------------------------------------------------------------
// Kernel 3: fp8 GEMM  D[j,s] = sum_k W'[j,k] * Xq[s,k],
//           out = relu(x + (0.1/256)*D).  mma.sync m16n8k32 e4m3, fp32 accum.
// CTA 128x128, BK=64 (bytes), 5-stage cp.async, 2 CTAs/SM, one barrier/iter.
// Operand fragments via conflict-free LDS.32 (80B row stride).
// ---------------------------------------------------------------------------
#define BM 128
#define BN 128
#define BK 64
#define NSTG 5
#define KT 8                       // CH / BK
#define SROW 80                    // smem row stride bytes (rows -> banks 20r mod 32)
#define A_ST (BM * SROW)           // 10240
#define B_ST (BN * SROW)           // 10240
#define STG_B (A_ST + B_ST)        // 20480
#define GEMM_SMEM (NSTG * STG_B + 128)   // 102528

__device__ __forceinline__ uint32_t cvta_s(const void* p) {
    return (uint32_t)__cvta_generic_to_shared(p);
}
__device__ __forceinline__ uint32_t lds32(uint32_t a) {
    uint32_t v;
    asm volatile("ld.shared.u32 %0, [%1];" : "=r"(v) : "r"(a));
    return v;
}

__global__ void __launch_bounds__(256, 2)
gemm_kernel(const float* __restrict__ x, float* __restrict__ out) {
    extern __shared__ char dsm[];
    int b  = blockIdx.z;
    int m0 = blockIdx.y * BM;
    int n0 = blockIdx.x * BN;
    int tid = threadIdx.x, lane = tid & 31, warp = tid >> 5;
    int wm = warp >> 2, wn = warp & 3;
    int g = lane >> 2, t = lane & 3;

    uint32_t base = (cvta_s(dsm) + 127u) & ~127u;

    const uint8_t* Wg = g_Wq + ((size_t)b * CH + m0) * CH;
    const uint8_t* Xg = g_Xq + ((size_t)b * SP + n0) * CH;

    // async copy of one K-stage (64 bytes per row) into buffer stg
    auto issue = [&](int kt, int stg) {
        uint32_t Ab = base + stg * STG_B;
        uint32_t Bb = Ab + A_ST;
        #pragma unroll
        for (int i = 0; i < 2; ++i) {
            int ch = tid + i * 256;                    // A: 128 rows x 4 chunks
            int r = ch >> 2, c = ch & 3;
            const void* src = Wg + (size_t)r * CH + kt * BK + c * 16;
            asm volatile("cp.async.cg.shared.global [%0], [%1], 16;"
                         :: "r"(Ab + r * SROW + c * 16), "l"(src));
        }
        #pragma unroll
        for (int i = 0; i < 2; ++i) {
            int ch = tid + i * 256;                    // B: 128 s-rows x 4 chunks
            int r = ch >> 2, c = ch & 3;
            const void* src = Xg + (size_t)r * CH + kt * BK + c * 16;
            asm volatile("cp.async.cg.shared.global [%0], [%1], 16;"
                         :: "r"(Bb + r * SROW + c * 16), "l"(src));
        }
        asm volatile("cp.async.commit_group;" ::: "memory");
    };

    float acc[4][4][4];
    #pragma unroll
    for (int i = 0; i < 4; ++i)
        #pragma unroll
        for (int j = 0; j < 4; ++j)
            #pragma unroll
            for (int k = 0; k < 4; ++k) acc[i][j][k] = 0.0f;

    issue(0, 0); issue(1, 1); issue(2, 2); issue(3, 3);

    for (int kt = 0; kt < KT; ++kt) {
        int stg = kt % NSTG;
        uint32_t Ab = base + stg * STG_B;
        uint32_t Bb = Ab + A_ST;

        asm volatile("cp.async.wait_group 3;" ::: "memory");
        __syncthreads();
        // refill (kt+4)%5 == (kt-1)%5: consumed at kt-1; all warps past the
        // barrier above finished kt-1 — safe without a second barrier.
        if (kt + 4 < KT) issue(kt + 4, (kt + 4) % NSTG);

        #pragma unroll
        for (int kk = 0; kk < BK; kk += 32) {
            uint32_t af[4][4], bf[4][2];
            #pragma unroll
            for (int mi = 0; mi < 4; ++mi) {
                uint32_t a0 = Ab + (wm * 64 + mi * 16 + g) * SROW + kk + t * 4;
                af[mi][0] = lds32(a0);                    // row g,   k 4t..4t+3
                af[mi][1] = lds32(a0 + 8 * SROW);         // row g+8, k 4t..4t+3
                af[mi][2] = lds32(a0 + 16);               // row g,   k 4t+16..
                af[mi][3] = lds32(a0 + 8 * SROW + 16);    // row g+8, k 4t+16..
            }
            #pragma unroll
            for (int nj = 0; nj < 4; ++nj) {
                uint32_t b0 = Bb + (wn * 32 + nj * 8 + g) * SROW + kk + t * 4;
                bf[nj][0] = lds32(b0);                    // col g, k 4t..4t+3
                bf[nj][1] = lds32(b0 + 16);               // col g, k 4t+16..
            }
            #pragma unroll
            for (int mi = 0; mi < 4; ++mi)
                #pragma unroll
                for (int nj = 0; nj < 4; ++nj)
                    asm volatile("mma.sync.aligned.m16n8k32.row.col.f32.e4m3.e4m3.f32 "
                                 "{%0,%1,%2,%3}, {%4,%5,%6,%7}, {%8,%9}, {%0,%1,%2,%3};"
                                 : "+f"(acc[mi][nj][0]), "+f"(acc[mi][nj][1]),
                                   "+f"(acc[mi][nj][2]), "+f"(acc[mi][nj][3])
                                 : "r"(af[mi][0]), "r"(af[mi][1]), "r"(af[mi][2]), "r"(af[mi][3]),
                                   "r"(bf[nj][0]), "r"(bf[nj][1]));
        }
    }

    // Epilogue: relu(x + (0.1/256)*D), fp32 residual read
    const float* Xr = x   + ((size_t)b * CH) * SP;
    float*       Og = out + ((size_t)b * CH) * SP;
    const float sc = 0.1f / 256.0f;
    #pragma unroll
    for (int mi = 0; mi < 4; ++mi) {
        #pragma unroll
        for (int h = 0; h < 2; ++h) {
            int row = m0 + wm * 64 + mi * 16 + h * 8 + g;
            #pragma unroll
            for (int nj = 0; nj < 4; ++nj) {
                int col = n0 + wn * 32 + nj * 8 + t * 2;
                size_t idx = (size_t)row * SP + col;
                float2 xv = *reinterpret_cast<const float2*>(Xr + idx);
                float r0 = fmaxf(xv.x + sc * acc[mi][nj][h * 2 + 0], 0.0f);
                float r1 = fmaxf(xv.y + sc * acc[mi][nj][h * 2 + 1], 0.0f);
                *reinterpret_cast<float2*>(Og + idx) = make_float2(r0, r1);
            }
        }
    }
}

// ---------------------------------------------------------------------------
extern "C" void kernel_launch(void* const* d_in, const int* in_sizes, int n_in,
                              void* d_out, int out_size) {
    (void)in_sizes; (void)n_in; (void)out_size;
    const float* x = (const float*)d_in[0];
    float* out = (float*)d_out;

    cudaFuncSetAttribute(gemm_kernel, cudaFuncAttributeMaxDynamicSharedMemorySize, GEMM_SMEM);

    prep_kernel<<<dim3(16, 8, BATCH), 256>>>(x);
    attn_kernel<<<dim3(4, BATCH), 256>>>();
    gemm_kernel<<<dim3(SP / BN, CH / BM, BATCH), 256, GEMM_SMEM>>>(x, out);
}